// round 3
// baseline (speedup 1.0000x reference)
#include <cuda_runtime.h>
#include <cstdint>
#include <cstddef>

#define T_STEPS 2048
#define NB      32
#define HDIM    256
#define G4H     1024
#define CLUSTER_SZ 8

// ---------------------------------------------------------------------------
// Scratch (device globals — no allocation allowed in kernel_launch)
// ---------------------------------------------------------------------------
__device__ float g_xw0[(size_t)NB * T_STEPS * G4H];    // 268 MB
__device__ float g_h0seq[(size_t)NB * T_STEPS * HDIM]; // 64 MB
__device__ float g_xw1[(size_t)NB * T_STEPS * G4H];    // 268 MB
__device__ float g_h1T[NB * HDIM];

// ---------------------------------------------------------------------------
// Packed fp32x2 helpers (Blackwell FFMA2 path — ptxas won't auto-fuse)
// ---------------------------------------------------------------------------
__device__ __forceinline__ uint64_t fma_x2(uint64_t a, uint64_t b, uint64_t c) {
    uint64_t d;
    asm("fma.rn.f32x2 %0, %1, %2, %3;" : "=l"(d) : "l"(a), "l"(b), "l"(c));
    return d;
}
__device__ __forceinline__ uint64_t pack2(float x, float y) {
    uint64_t d;
    asm("mov.b64 %0, {%1, %2};" : "=l"(d) : "f"(x), "f"(y));
    return d;
}
__device__ __forceinline__ void unpack2(uint64_t v, float& lo, float& hi) {
    asm("mov.b64 {%0, %1}, %2;" : "=f"(lo), "=f"(hi) : "l"(v));
}
__device__ __forceinline__ void lds_v2u64(uint64_t& a, uint64_t& b, uint32_t addr) {
    asm volatile("ld.shared.v2.u64 {%0, %1}, [%2];" : "=l"(a), "=l"(b) : "r"(addr));
}

// ---------------------------------------------------------------------------
// GEMM: out[M x 1024] = A[M x K] @ W[K x 1024] + bias   (M = 65536)
// 64x64 block tile, K chunked by 128 (66 KB smem -> 3 CTAs/SM), 256 threads,
// 4x4 per-thread tile computed with packed FFMA2.
// ---------------------------------------------------------------------------
template <int K>
__global__ __launch_bounds__(256)
void gemm_xw(const float* __restrict__ A, const float* __restrict__ W,
             const float* __restrict__ bias, float* __restrict__ out) {
    extern __shared__ float sm[];
    float* a_s = sm;               // [128][65] transposed A tile
    float* w_s = sm + 128 * 65;    // [128][64]

    const int tid = threadIdx.x;
    const long m0 = (long)blockIdx.x * 64;
    const int  n0 = blockIdx.y * 64;

    const int tn = (tid & 15) << 2;
    const int tm = (tid >> 4) << 2;

    const uint32_t ws_b = (uint32_t)__cvta_generic_to_shared(w_s);

    uint64_t acc01[4], acc23[4];
#pragma unroll
    for (int i = 0; i < 4; i++) { acc01[i] = 0ull; acc23[i] = 0ull; }

    for (int k0 = 0; k0 < K; k0 += 128) {
        for (int idx = tid; idx < 64 * 128; idx += 256) {
            int r = idx >> 7;
            int k = idx & 127;
            a_s[k * 65 + r] = A[(m0 + r) * K + k0 + k];
        }
        for (int idx = tid; idx < 128 * 16; idx += 256) {
            int k = idx >> 4, c4 = idx & 15;
            *reinterpret_cast<float4*>(w_s + k * 64 + c4 * 4) =
                *reinterpret_cast<const float4*>(W + (size_t)(k0 + k) * G4H + n0 + c4 * 4);
        }
        __syncthreads();

#pragma unroll 8
        for (int k = 0; k < 128; k++) {
            const float* ap = a_s + k * 65 + tm;
            float a0 = ap[0], a1 = ap[1], a2 = ap[2], a3 = ap[3];
            uint64_t b01, b23;
            lds_v2u64(b01, b23, ws_b + (uint32_t)(k * 64 + tn) * 4u);
            uint64_t aa;
            aa = pack2(a0, a0);
            acc01[0] = fma_x2(aa, b01, acc01[0]); acc23[0] = fma_x2(aa, b23, acc23[0]);
            aa = pack2(a1, a1);
            acc01[1] = fma_x2(aa, b01, acc01[1]); acc23[1] = fma_x2(aa, b23, acc23[1]);
            aa = pack2(a2, a2);
            acc01[2] = fma_x2(aa, b01, acc01[2]); acc23[2] = fma_x2(aa, b23, acc23[2]);
            aa = pack2(a3, a3);
            acc01[3] = fma_x2(aa, b01, acc01[3]); acc23[3] = fma_x2(aa, b23, acc23[3]);
        }
        __syncthreads();
    }

    float4 bv = *reinterpret_cast<const float4*>(bias + n0 + tn);
#pragma unroll
    for (int i = 0; i < 4; i++) {
        float4 o;
        unpack2(acc01[i], o.x, o.y);
        unpack2(acc23[i], o.z, o.w);
        o.x += bv.x; o.y += bv.y; o.z += bv.z; o.w += bv.w;
        *reinterpret_cast<float4*>(out + (m0 + tm + i) * G4H + n0 + tn) = o;
    }
}

// ---------------------------------------------------------------------------
// LSTM recurrence, 256 threads / CTA, k-split dot.
// Cluster of 8 CTAs per batch-pair; CTA rank r owns hidden units
// [r*32, r*32+32) => 128 gate-columns. U slice in SMEM, swizzled
// w_s[gate][k4][lane] float4 layout (conflict-free LDS.128).
// Thread (half, g, u): dot over k in [half*128, half*128+128) for 2 batches
// (32 float4 iters, packed FFMA2). Partials reduced via SMEM; warps 0/1
// combine gates (c-state + xw prefetch in their registers) and broadcast
// h(t) to all 8 cluster CTAs via DSMEM. One barrier.cluster per step,
// h double-buffered by parity.
// ---------------------------------------------------------------------------
__device__ __forceinline__ float sigmoidf_(float x) {
    return __fdividef(1.f, 1.f + __expf(-x));
}

#define CLUSTER_SYNC() do { \
    asm volatile("barrier.cluster.arrive.aligned;" ::: "memory"); \
    asm volatile("barrier.cluster.wait.aligned;"   ::: "memory"); \
} while (0)

#define WS_FLOATS   (128 * HDIM)                  // 32768 floats = 128 KB
#define HBUF_OFF    WS_FLOATS                     // [2 parity][2 batch][256]
#define PART_OFF    (HBUF_OFF + 2 * 2 * HDIM)     // [2 half][4 gate][2 b][32]
#define REC_FLOATS  (PART_OFF + 512)

template <bool STORE_SEQ>
__global__ __launch_bounds__(256, 1) __cluster_dims__(CLUSTER_SZ, 1, 1)
void lstm_rec(const float* __restrict__ xw, const float* __restrict__ U,
              float* __restrict__ out_seq, float* __restrict__ out_last) {
    extern __shared__ float sm[];
    float* w_s  = sm;
    float* hbuf = sm + HBUF_OFF;
    float* part = sm + PART_OFF;

    const int tid  = threadIdx.x;       // 256
    const int half = tid >> 7;          // k-half
    const int g    = (tid >> 5) & 3;    // gate 0..3 (i,f,g,o)
    const int u    = tid & 31;          // unit within CTA slice

    uint32_t rank;
    asm("mov.u32 %0, %%cluster_ctarank;" : "=r"(rank));
    const int cid = blockIdx.x >> 3;
    const int u0  = (int)rank * 32;
    const int b0  = cid * 2;

    // Load U slice into swizzled SMEM layout:
    //   (k, c) -> float idx ((c>>5)*64 + (k>>2))*128 + (c&31)*4 + (k&3)
    for (int idx = tid; idx < 128 * HDIM; idx += 256) {
        int k = idx >> 7;          // 0..255
        int c = idx & 127;         // gate*32 + unit
        int col = (c >> 5) * HDIM + u0 + (c & 31);
        w_s[(((c >> 5) * 64 + (k >> 2)) << 7) + ((c & 31) << 2) + (k & 3)] =
            U[(size_t)k * G4H + col];
    }
    // Zero h double-buffer + partials
    for (int idx = tid; idx < 2 * 2 * HDIM + 512; idx += 256) hbuf[idx] = 0.f;

    // Combine-thread state (warps 0/1): cell state + prefetched xw gates
    const bool is_comb = (tid < 64);
    const int  cb  = tid >> 5;          // batch within pair
    const int  cu  = tid & 31;          // unit
    float cst = 0.f;
    float xwr0 = 0.f, xwr1 = 0.f, xwr2 = 0.f, xwr3 = 0.f;
    const size_t xbase = (size_t)(b0 + cb) * T_STEPS * G4H + u0 + cu;
    if (is_comb) {
        xwr0 = xw[xbase + 0 * HDIM];
        xwr1 = xw[xbase + 1 * HDIM];
        xwr2 = xw[xbase + 2 * HDIM];
        xwr3 = xw[xbase + 3 * HDIM];
    }

    CLUSTER_SYNC();   // all peers' hbuf zeroed before any DSMEM write lands

    const uint32_t smem_b = (uint32_t)__cvta_generic_to_shared(sm);
    const uint32_t hbuf_b = smem_b + HBUF_OFF * 4u;
    const uint32_t part_b = smem_b + PART_OFF * 4u;
    // per-thread w base: gate row (32 KB) + k-half (16 KB) + lane (16 B)
    const uint32_t w_b = smem_b + (uint32_t)g * 32768u +
                         (uint32_t)half * 16384u + (uint32_t)u * 16u;

    for (int t = 0; t < T_STEPS; t++) {
        const int rd = (t + 1) & 1;  // parity holding h(t-1)
        const uint32_t h0_b = hbuf_b + (uint32_t)(rd * 2 * HDIM + half * 128) * 4u;
        const uint32_t h1_b = h0_b + HDIM * 4u;

        uint64_t a01 = 0ull, a23 = 0ull, c01 = 0ull, c23 = 0ull;
#pragma unroll
        for (int k4 = 0; k4 < 32; k4++) {
            uint64_t w01, w23, p01, p23, q01, q23;
            lds_v2u64(w01, w23, w_b + (uint32_t)k4 * 512u);  // conflict-free
            lds_v2u64(p01, p23, h0_b + (uint32_t)k4 * 16u);  // broadcast
            lds_v2u64(q01, q23, h1_b + (uint32_t)k4 * 16u);  // broadcast
            a01 = fma_x2(w01, p01, a01);
            a23 = fma_x2(w23, p23, a23);
            c01 = fma_x2(w01, q01, c01);
            c23 = fma_x2(w23, q23, c23);
        }
        float s0, s1, s2, s3, r0, r1, r2, r3;
        unpack2(a01, s0, s1); unpack2(a23, s2, s3);
        unpack2(c01, r0, r1); unpack2(c23, r2, r3);
        float pa = (s0 + s1) + (s2 + s3);
        float pb = (r0 + r1) + (r2 + r3);

        // part[half][gate][batch][unit]
        part[((half * 4 + g) * 2 + 0) * 32 + u] = pa;
        part[((half * 4 + g) * 2 + 1) * 32 + u] = pb;
        __syncthreads();

        if (is_comb) {
            const uint32_t p0 = part_b + (uint32_t)(cb * 32 + cu) * 4u;
            float zi = xwr0 + sm[PART_OFF + (0 * 2 + cb) * 32 + cu]
                            + sm[PART_OFF + ((4 + 0) * 2 + cb) * 32 + cu];
            float zf = xwr1 + sm[PART_OFF + (1 * 2 + cb) * 32 + cu]
                            + sm[PART_OFF + ((4 + 1) * 2 + cb) * 32 + cu];
            float zg = xwr2 + sm[PART_OFF + (2 * 2 + cb) * 32 + cu]
                            + sm[PART_OFF + ((4 + 2) * 2 + cb) * 32 + cu];
            float zo = xwr3 + sm[PART_OFF + (3 * 2 + cb) * 32 + cu]
                            + sm[PART_OFF + ((4 + 3) * 2 + cb) * 32 + cu];
            (void)p0;

            // prefetch next step's xw (consumed next iteration)
            if (t + 1 < T_STEPS) {
                const size_t xb = xbase + (size_t)(t + 1) * G4H;
                xwr0 = xw[xb + 0 * HDIM];
                xwr1 = xw[xb + 1 * HDIM];
                xwr2 = xw[xb + 2 * HDIM];
                xwr3 = xw[xb + 3 * HDIM];
            }

            float iv = sigmoidf_(zi);
            float fv = sigmoidf_(zf);
            float ov = sigmoidf_(zo);
            cst = fmaf(fv, cst, iv * zg);  // linear candidate activation
            float h = ov * cst;            // linear output activation

            if (STORE_SEQ) {
                out_seq[((size_t)(b0 + cb) * T_STEPS + t) * HDIM + u0 + cu] = h;
            } else if (t == T_STEPS - 1) {
                out_last[(b0 + cb) * HDIM + u0 + cu] = h;
            }

            // Broadcast h(t) to all 8 cluster CTAs (write parity t&1)
            uint32_t laddr = hbuf_b +
                ((uint32_t)((t & 1) * 2 * HDIM + cb * HDIM + u0 + cu) << 2);
#pragma unroll
            for (int r = 0; r < CLUSTER_SZ; r++) {
                uint32_t raddr;
                asm volatile("mapa.shared::cluster.u32 %0, %1, %2;"
                             : "=r"(raddr) : "r"(laddr), "r"(r));
                asm volatile("st.shared::cluster.f32 [%0], %1;"
                             :: "r"(raddr), "f"(h) : "memory");
            }
        }
        // release-arrive orders DSMEM stores before peers' next-step reads;
        // also acts as the CTA-wide barrier protecting `part` reuse.
        CLUSTER_SYNC();
    }
}

// ---------------------------------------------------------------------------
// Final FC: out[32,1,128] = h1T[32,256] @ Wfc[256,128] + bfc
// ---------------------------------------------------------------------------
__global__ __launch_bounds__(128)
void fc_kernel(const float* __restrict__ h, const float* __restrict__ Wfc,
               const float* __restrict__ bfc, float* __restrict__ out) {
    const int b = blockIdx.x;
    const int j = threadIdx.x;
    const float* hb = h + b * HDIM;
    float acc = bfc[j];
#pragma unroll 16
    for (int k = 0; k < HDIM; k++)
        acc = fmaf(hb[k], Wfc[k * 128 + j], acc);
    out[b * 128 + j] = acc;
}

// ---------------------------------------------------------------------------
// Launch
// ---------------------------------------------------------------------------
#define GEMM_SMEM ((128 * 65 + 128 * 64) * 4)   // 66048
#define REC_SMEM  (REC_FLOATS * 4)              // 137216

extern "C" void kernel_launch(void* const* d_in, const int* in_sizes, int n_in,
                              void* d_out, int out_size) {
    const float* x   = (const float*)d_in[0];
    const float* W0  = (const float*)d_in[1];
    const float* U0  = (const float*)d_in[2];
    const float* b0v = (const float*)d_in[3];
    const float* W1  = (const float*)d_in[4];
    const float* U1  = (const float*)d_in[5];
    const float* b1v = (const float*)d_in[6];
    const float* Wfc = (const float*)d_in[7];
    const float* bfc = (const float*)d_in[8];
    float* out = (float*)d_out;

    float *xw0, *h0seq, *xw1, *h1T;
    cudaGetSymbolAddress((void**)&xw0,   g_xw0);
    cudaGetSymbolAddress((void**)&h0seq, g_h0seq);
    cudaGetSymbolAddress((void**)&xw1,   g_xw1);
    cudaGetSymbolAddress((void**)&h1T,   g_h1T);

    cudaFuncSetAttribute(gemm_xw<128>, cudaFuncAttributeMaxDynamicSharedMemorySize, GEMM_SMEM);
    cudaFuncSetAttribute(gemm_xw<256>, cudaFuncAttributeMaxDynamicSharedMemorySize, GEMM_SMEM);
    cudaFuncSetAttribute(lstm_rec<true>,  cudaFuncAttributeMaxDynamicSharedMemorySize, REC_SMEM);
    cudaFuncSetAttribute(lstm_rec<false>, cudaFuncAttributeMaxDynamicSharedMemorySize, REC_SMEM);

    const long M = (long)NB * T_STEPS;  // 65536 rows

    gemm_xw<128><<<dim3((unsigned)(M / 64), G4H / 64), 256, GEMM_SMEM>>>(x, W0, b0v, xw0);
    lstm_rec<true><<<NB / 2 * CLUSTER_SZ, 256, REC_SMEM>>>(xw0, U0, h0seq, nullptr);
    gemm_xw<256><<<dim3((unsigned)(M / 64), G4H / 64), 256, GEMM_SMEM>>>(h0seq, W1, b1v, xw1);
    lstm_rec<false><<<NB / 2 * CLUSTER_SZ, 256, REC_SMEM>>>(xw1, U1, nullptr, h1T);
    fc_kernel<<<NB, 128>>>(h1T, Wfc, bfc, out);
}

// round 4
// speedup vs baseline: 1.2775x; 1.2775x over previous
#include <cuda_runtime.h>
#include <cstdint>
#include <cstddef>

#define T_STEPS 2048
#define NB      32
#define HDIM    256
#define G4H     1024
#define CLUSTER_SZ 8

// ---------------------------------------------------------------------------
// Scratch (device globals — no allocation allowed in kernel_launch)
// ---------------------------------------------------------------------------
__device__ float g_xw0[(size_t)NB * T_STEPS * G4H];    // 268 MB
__device__ float g_h0seq[(size_t)NB * T_STEPS * HDIM]; // 64 MB
__device__ float g_xw1[(size_t)NB * T_STEPS * G4H];    // 268 MB
__device__ float g_h1T[NB * HDIM];

// ---------------------------------------------------------------------------
// Packed fp32x2 helpers (Blackwell FFMA2 path — ptxas won't auto-fuse)
// ---------------------------------------------------------------------------
__device__ __forceinline__ uint64_t fma_x2(uint64_t a, uint64_t b, uint64_t c) {
    uint64_t d;
    asm("fma.rn.f32x2 %0, %1, %2, %3;" : "=l"(d) : "l"(a), "l"(b), "l"(c));
    return d;
}
__device__ __forceinline__ uint64_t pack2(float x, float y) {
    uint64_t d;
    asm("mov.b64 %0, {%1, %2};" : "=l"(d) : "f"(x), "f"(y));
    return d;
}
__device__ __forceinline__ void unpack2(uint64_t v, float& lo, float& hi) {
    asm("mov.b64 {%0, %1}, %2;" : "=f"(lo), "=f"(hi) : "l"(v));
}
__device__ __forceinline__ void lds_v2u64(uint64_t& a, uint64_t& b, uint32_t addr) {
    asm volatile("ld.shared.v2.u64 {%0, %1}, [%2];" : "=l"(a), "=l"(b) : "r"(addr));
}

// mbarrier primitives (in-tree proven forms)
#define MBARRIER_INIT(addr, count) \
    asm volatile("mbarrier.init.shared.b64 [%0], %1;" \
                 :: "r"((uint32_t)(addr)), "r"((uint32_t)(count)) : "memory")

#define MBARRIER_WAIT_PARITY(mbar_smem_addr, phase_parity) do { \
    uint32_t _mbar = (uint32_t)(mbar_smem_addr); \
    uint32_t _parity = (uint32_t)(phase_parity); \
    uint32_t _done; \
    asm volatile( \
        "{\n\t" \
        ".reg .pred p;\n\t" \
        "mbarrier.try_wait.parity.acquire.cta.shared::cta.b64 p, [%1], %2;\n\t" \
        "selp.b32 %0, 1, 0, p;\n\t" \
        "}" \
        : "=r"(_done) : "r"(_mbar), "r"(_parity) : "memory"); \
    if (!_done) { \
        asm volatile( \
            "{\n\t" \
            ".reg .pred P1;\n\t" \
            "WAIT_LOOP_%=:\n\t" \
            "mbarrier.try_wait.parity.acquire.cta.shared::cta.b64 P1, [%0], %1, 0x989680;\n\t" \
            "@P1 bra.uni WAIT_DONE_%=;\n\t" \
            "bra.uni WAIT_LOOP_%=;\n\t" \
            "WAIT_DONE_%=:\n\t" \
            "}" \
            :: "r"(_mbar), "r"(_parity) : "memory"); \
    } \
} while(0)

#define CLUSTER_SYNC() do { \
    asm volatile("barrier.cluster.arrive.aligned;" ::: "memory"); \
    asm volatile("barrier.cluster.wait.aligned;"   ::: "memory"); \
} while (0)

// ---------------------------------------------------------------------------
// GEMM: out[M x 1024] = A[M x K] @ W[K x 1024] + bias   (M = 65536)
// ---------------------------------------------------------------------------
template <int K>
__global__ __launch_bounds__(256)
void gemm_xw(const float* __restrict__ A, const float* __restrict__ W,
             const float* __restrict__ bias, float* __restrict__ out) {
    extern __shared__ float sm[];
    float* a_s = sm;               // [128][65] transposed A tile
    float* w_s = sm + 128 * 65;    // [128][64]

    const int tid = threadIdx.x;
    const long m0 = (long)blockIdx.x * 64;
    const int  n0 = blockIdx.y * 64;

    const int tn = (tid & 15) << 2;
    const int tm = (tid >> 4) << 2;

    const uint32_t ws_b = (uint32_t)__cvta_generic_to_shared(w_s);

    uint64_t acc01[4], acc23[4];
#pragma unroll
    for (int i = 0; i < 4; i++) { acc01[i] = 0ull; acc23[i] = 0ull; }

    for (int k0 = 0; k0 < K; k0 += 128) {
        for (int idx = tid; idx < 64 * 128; idx += 256) {
            int r = idx >> 7;
            int k = idx & 127;
            a_s[k * 65 + r] = A[(m0 + r) * K + k0 + k];
        }
        for (int idx = tid; idx < 128 * 16; idx += 256) {
            int k = idx >> 4, c4 = idx & 15;
            *reinterpret_cast<float4*>(w_s + k * 64 + c4 * 4) =
                *reinterpret_cast<const float4*>(W + (size_t)(k0 + k) * G4H + n0 + c4 * 4);
        }
        __syncthreads();

#pragma unroll 8
        for (int k = 0; k < 128; k++) {
            const float* ap = a_s + k * 65 + tm;
            float a0 = ap[0], a1 = ap[1], a2 = ap[2], a3 = ap[3];
            uint64_t b01, b23;
            lds_v2u64(b01, b23, ws_b + (uint32_t)(k * 64 + tn) * 4u);
            uint64_t aa;
            aa = pack2(a0, a0);
            acc01[0] = fma_x2(aa, b01, acc01[0]); acc23[0] = fma_x2(aa, b23, acc23[0]);
            aa = pack2(a1, a1);
            acc01[1] = fma_x2(aa, b01, acc01[1]); acc23[1] = fma_x2(aa, b23, acc23[1]);
            aa = pack2(a2, a2);
            acc01[2] = fma_x2(aa, b01, acc01[2]); acc23[2] = fma_x2(aa, b23, acc23[2]);
            aa = pack2(a3, a3);
            acc01[3] = fma_x2(aa, b01, acc01[3]); acc23[3] = fma_x2(aa, b23, acc23[3]);
        }
        __syncthreads();
    }

    float4 bv = *reinterpret_cast<const float4*>(bias + n0 + tn);
#pragma unroll
    for (int i = 0; i < 4; i++) {
        float4 o;
        unpack2(acc01[i], o.x, o.y);
        unpack2(acc23[i], o.z, o.w);
        o.x += bv.x; o.y += bv.y; o.z += bv.z; o.w += bv.w;
        *reinterpret_cast<float4*>(out + (m0 + tm + i) * G4H + n0 + tn) = o;
    }
}

// ---------------------------------------------------------------------------
// LSTM recurrence, mbarrier dataflow (NO per-step cluster barrier).
// Cluster of 8 CTAs per batch-pair; CTA rank r owns units [r*32, r*32+32).
// Per CTA: 2 parity mbarriers, arrive count 512 (8 CTAs x 64 combine thr).
// Step: wait local mbar (h(t-1) arrived from all producers) -> k-split dot
// (swizzled U in SMEM, FFMA2) -> partials via SMEM + __syncthreads ->
// combine warps compute h, remote-store slice to all 8 peers, remote
// mbarrier.arrive on each peer. WAR safety is transitive through the
// arrive chain (producer arrives only after its own dot reads finished).
// ---------------------------------------------------------------------------
__device__ __forceinline__ float sigmoidf_(float x) {
    return __fdividef(1.f, 1.f + __expf(-x));
}

#define WS_FLOATS   (128 * HDIM)                  // 32768 floats = 128 KB
#define HBUF_OFF    WS_FLOATS                     // [2 parity][2 batch][256]
#define PART_OFF    (HBUF_OFF + 2 * 2 * HDIM)     // [2 half][4 gate][2 b][32]
#define MBAR_OFF    (PART_OFF + 512)              // 2 x u64, 8B aligned
#define REC_FLOATS  (MBAR_OFF + 8)

template <bool STORE_SEQ>
__global__ __launch_bounds__(256, 1) __cluster_dims__(CLUSTER_SZ, 1, 1)
void lstm_rec(const float* __restrict__ xw, const float* __restrict__ U,
              float* __restrict__ out_seq, float* __restrict__ out_last) {
    extern __shared__ float sm[];
    float* w_s  = sm;
    float* hbuf = sm + HBUF_OFF;
    float* part = sm + PART_OFF;

    const int tid  = threadIdx.x;       // 256
    const int half = tid >> 7;          // k-half
    const int g    = (tid >> 5) & 3;    // gate 0..3 (i,f,g,o)
    const int u    = tid & 31;          // unit within CTA slice

    uint32_t rank;
    asm("mov.u32 %0, %%cluster_ctarank;" : "=r"(rank));
    const int cid = blockIdx.x >> 3;
    const int u0  = (int)rank * 32;
    const int b0  = cid * 2;

    const uint32_t smem_b = (uint32_t)__cvta_generic_to_shared(sm);
    const uint32_t mbar_b = smem_b + MBAR_OFF * 4u;

    if (tid == 0) {
        MBARRIER_INIT(mbar_b,      512);   // parity buffer 0
        MBARRIER_INIT(mbar_b + 8,  512);   // parity buffer 1
    }

    // Load U slice into swizzled SMEM layout:
    //   (k, c) -> float idx ((c>>5)*64 + (k>>2))*128 + (c&31)*4 + (k&3)
    for (int idx = tid; idx < 128 * HDIM; idx += 256) {
        int k = idx >> 7;          // 0..255
        int c = idx & 127;         // gate*32 + unit
        int col = (c >> 5) * HDIM + u0 + (c & 31);
        w_s[(((c >> 5) * 64 + (k >> 2)) << 7) + ((c & 31) << 2) + (k & 3)] =
            U[(size_t)k * G4H + col];
    }
    // Zero h double-buffer + partials
    for (int idx = tid; idx < 2 * 2 * HDIM + 512; idx += 256) hbuf[idx] = 0.f;
    __syncthreads();

    // Combine-thread state (warps 0/1)
    const bool is_comb = (tid < 64);
    const int  cb  = tid >> 5;          // batch within pair
    const int  cu  = tid & 31;          // unit
    float cst = 0.f;
    float xwr0 = 0.f, xwr1 = 0.f, xwr2 = 0.f, xwr3 = 0.f;
    const size_t xbase = (size_t)(b0 + cb) * T_STEPS * G4H + u0 + cu;
    uint32_t ra_base[CLUSTER_SZ];       // mapa'd peer SMEM bases (combine only)
    if (is_comb) {
        xwr0 = xw[xbase + 0 * HDIM];
        xwr1 = xw[xbase + 1 * HDIM];
        xwr2 = xw[xbase + 2 * HDIM];
        xwr3 = xw[xbase + 3 * HDIM];
#pragma unroll
        for (int r = 0; r < CLUSTER_SZ; r++) {
            asm volatile("mapa.shared::cluster.u32 %0, %1, %2;"
                         : "=r"(ra_base[r]) : "r"(smem_b), "r"(r));
        }
    }

    // mbarriers + zeroed hbuf must be cluster-visible before any peer store.
    CLUSTER_SYNC();

    const uint32_t hbuf_b = smem_b + HBUF_OFF * 4u;
    const uint32_t w_b = smem_b + (uint32_t)g * 32768u +
                         (uint32_t)half * 16384u + (uint32_t)u * 16u;

    int ph0 = 0, ph1 = 0;

    for (int t = 0; t < T_STEPS; t++) {
        // Wait for h(t-1): it lives in buf[(t+1)&1], signaled on mbar[(t+1)&1]
        if (t > 0) {
            if (t & 1) { MBARRIER_WAIT_PARITY(mbar_b,     ph0); ph0 ^= 1; }
            else       { MBARRIER_WAIT_PARITY(mbar_b + 8, ph1); ph1 ^= 1; }
        }

        const int rd = (t + 1) & 1;
        const uint32_t h0_b = hbuf_b + (uint32_t)(rd * 2 * HDIM + half * 128) * 4u;
        const uint32_t h1_b = h0_b + HDIM * 4u;

        uint64_t a01 = 0ull, a23 = 0ull, c01 = 0ull, c23 = 0ull;
#pragma unroll
        for (int k4 = 0; k4 < 32; k4++) {
            uint64_t w01, w23, p01, p23, q01, q23;
            lds_v2u64(w01, w23, w_b + (uint32_t)k4 * 512u);  // conflict-free
            lds_v2u64(p01, p23, h0_b + (uint32_t)k4 * 16u);  // broadcast
            lds_v2u64(q01, q23, h1_b + (uint32_t)k4 * 16u);  // broadcast
            a01 = fma_x2(w01, p01, a01);
            a23 = fma_x2(w23, p23, a23);
            c01 = fma_x2(w01, q01, c01);
            c23 = fma_x2(w23, q23, c23);
        }
        float s0, s1, s2, s3, r0, r1, r2, r3;
        unpack2(a01, s0, s1); unpack2(a23, s2, s3);
        unpack2(c01, r0, r1); unpack2(c23, r2, r3);
        float pa = (s0 + s1) + (s2 + s3);
        float pb = (r0 + r1) + (r2 + r3);

        // part[half][gate][batch][unit]
        part[((half * 4 + g) * 2 + 0) * 32 + u] = pa;
        part[((half * 4 + g) * 2 + 1) * 32 + u] = pb;
        __syncthreads();

        if (is_comb) {
            float zi = xwr0 + part[(0 * 2 + cb) * 32 + cu]
                            + part[((4 + 0) * 2 + cb) * 32 + cu];
            float zf = xwr1 + part[(1 * 2 + cb) * 32 + cu]
                            + part[((4 + 1) * 2 + cb) * 32 + cu];
            float zg = xwr2 + part[(2 * 2 + cb) * 32 + cu]
                            + part[((4 + 2) * 2 + cb) * 32 + cu];
            float zo = xwr3 + part[(3 * 2 + cb) * 32 + cu]
                            + part[((4 + 3) * 2 + cb) * 32 + cu];

            // prefetch next step's xw
            if (t + 1 < T_STEPS) {
                const size_t xb = xbase + (size_t)(t + 1) * G4H;
                xwr0 = xw[xb + 0 * HDIM];
                xwr1 = xw[xb + 1 * HDIM];
                xwr2 = xw[xb + 2 * HDIM];
                xwr3 = xw[xb + 3 * HDIM];
            }

            float iv = sigmoidf_(zi);
            float fv = sigmoidf_(zf);
            float ov = sigmoidf_(zo);
            cst = fmaf(fv, cst, iv * zg);  // linear candidate activation
            float h = ov * cst;            // linear output activation

            if (STORE_SEQ) {
                out_seq[((size_t)(b0 + cb) * T_STEPS + t) * HDIM + u0 + cu] = h;
            } else if (t == T_STEPS - 1) {
                out_last[(b0 + cb) * HDIM + u0 + cu] = h;
            }

            if (t + 1 < T_STEPS) {
                // Push h(t) slice to all 8 peers' buf[t&1], then arrive on
                // each peer's mbar[t&1]. arrive (release) orders the store.
                const uint32_t hoff = HBUF_OFF * 4u +
                    ((uint32_t)((t & 1) * 2 * HDIM + cb * HDIM + u0 + cu) << 2);
                const uint32_t moff = MBAR_OFF * 4u + ((uint32_t)(t & 1) << 3);
#pragma unroll
                for (int r = 0; r < CLUSTER_SZ; r++) {
                    asm volatile("st.shared::cluster.f32 [%0], %1;"
                                 :: "r"(ra_base[r] + hoff), "f"(h) : "memory");
                }
#pragma unroll
                for (int r = 0; r < CLUSTER_SZ; r++) {
                    asm volatile("mbarrier.arrive.shared::cluster.b64 _, [%0];"
                                 :: "r"(ra_base[r] + moff) : "memory");
                }
            }
        }
        // No end-of-step barrier: next-step part/hbuf writes are ordered
        // behind the mbar wait, which requires this CTA's own arrives.
    }
}

// ---------------------------------------------------------------------------
// Final FC: out[32,1,128] = h1T[32,256] @ Wfc[256,128] + bfc
// ---------------------------------------------------------------------------
__global__ __launch_bounds__(128)
void fc_kernel(const float* __restrict__ h, const float* __restrict__ Wfc,
               const float* __restrict__ bfc, float* __restrict__ out) {
    const int b = blockIdx.x;
    const int j = threadIdx.x;
    const float* hb = h + b * HDIM;
    float acc = bfc[j];
#pragma unroll 16
    for (int k = 0; k < HDIM; k++)
        acc = fmaf(hb[k], Wfc[k * 128 + j], acc);
    out[b * 128 + j] = acc;
}

// ---------------------------------------------------------------------------
// Launch
// ---------------------------------------------------------------------------
#define GEMM_SMEM ((128 * 65 + 128 * 64) * 4)   // 66048
#define REC_SMEM  (REC_FLOATS * 4)              // ~137 KB

extern "C" void kernel_launch(void* const* d_in, const int* in_sizes, int n_in,
                              void* d_out, int out_size) {
    const float* x   = (const float*)d_in[0];
    const float* W0  = (const float*)d_in[1];
    const float* U0  = (const float*)d_in[2];
    const float* b0v = (const float*)d_in[3];
    const float* W1  = (const float*)d_in[4];
    const float* U1  = (const float*)d_in[5];
    const float* b1v = (const float*)d_in[6];
    const float* Wfc = (const float*)d_in[7];
    const float* bfc = (const float*)d_in[8];
    float* out = (float*)d_out;

    float *xw0, *h0seq, *xw1, *h1T;
    cudaGetSymbolAddress((void**)&xw0,   g_xw0);
    cudaGetSymbolAddress((void**)&h0seq, g_h0seq);
    cudaGetSymbolAddress((void**)&xw1,   g_xw1);
    cudaGetSymbolAddress((void**)&h1T,   g_h1T);

    cudaFuncSetAttribute(gemm_xw<128>, cudaFuncAttributeMaxDynamicSharedMemorySize, GEMM_SMEM);
    cudaFuncSetAttribute(gemm_xw<256>, cudaFuncAttributeMaxDynamicSharedMemorySize, GEMM_SMEM);
    cudaFuncSetAttribute(lstm_rec<true>,  cudaFuncAttributeMaxDynamicSharedMemorySize, REC_SMEM);
    cudaFuncSetAttribute(lstm_rec<false>, cudaFuncAttributeMaxDynamicSharedMemorySize, REC_SMEM);

    const long M = (long)NB * T_STEPS;  // 65536 rows

    gemm_xw<128><<<dim3((unsigned)(M / 64), G4H / 64), 256, GEMM_SMEM>>>(x, W0, b0v, xw0);
    lstm_rec<true><<<NB / 2 * CLUSTER_SZ, 256, REC_SMEM>>>(xw0, U0, h0seq, nullptr);
    gemm_xw<256><<<dim3((unsigned)(M / 64), G4H / 64), 256, GEMM_SMEM>>>(h0seq, W1, b1v, xw1);
    lstm_rec<false><<<NB / 2 * CLUSTER_SZ, 256, REC_SMEM>>>(xw1, U1, nullptr, h1T);
    fc_kernel<<<NB, 128>>>(h1T, Wfc, bfc, out);
}